// round 3
// baseline (speedup 1.0000x reference)
#include <cuda_runtime.h>

// Geometry fixed by the reference: (2,1,192,192,192) fp32 x3 -> scalar
constexpr int BATCH = 2, D = 192, H = 192, W = 192;
constexpr int DS = H * W;             // plane stride (elements)
constexpr int XV = 4;                 // x-values per thread (one float4, 2 packed pairs)
constexpr int ZC = 12;                // z planes per thread
constexpr int GX = W / XV;            // 48
constexpr int NZ = D / ZC;            // 16
constexpr int THREADS = 128;
constexpr long long NVOX = (long long)BATCH * D * H * W;
constexpr int NBLOCKS = BATCH * H * GX * NZ / THREADS;   // 2304

__device__ double   g_accum = 0.0;
__device__ unsigned g_done  = 0;

typedef unsigned long long u64;

// packed-f32x2 constants (bit patterns)
#define TWO2  0x4000000040000000ULL   // (2.0f, 2.0f)
#define NEG12 0xBF800000BF800000ULL   // (-1.0f, -1.0f)
#define EPS2  0x2EDBE6FF2EDBE6FFULL   // (1e-10f, 1e-10f)

__device__ __forceinline__ u64 pk(float lo, float hi) {
    u64 r; asm("mov.b64 %0, {%1,%2};" : "=l"(r) : "f"(lo), "f"(hi)); return r;
}
__device__ __forceinline__ void upk(u64 v, float& lo, float& hi) {
    asm("mov.b64 {%0,%1}, %2;" : "=f"(lo), "=f"(hi) : "l"(v));
}
__device__ __forceinline__ u64 fma2(u64 a, u64 b, u64 c) {
    u64 d; asm("fma.rn.f32x2 %0, %1, %2, %3;" : "=l"(d) : "l"(a), "l"(b), "l"(c)); return d;
}
__device__ __forceinline__ u64 add2(u64 a, u64 b) {
    u64 d; asm("add.rn.f32x2 %0, %1, %2;" : "=l"(d) : "l"(a), "l"(b)); return d;
}
__device__ __forceinline__ u64 sub2(u64 a, u64 b) { return fma2(b, NEG12, a); }  // a-b

__device__ __forceinline__ float fsqrt_a(float x) {
    float y; asm("sqrt.approx.f32 %0, %1;" : "=f"(y) : "f"(x)); return y;
}
__device__ __forceinline__ float htanh(float x) {
    float y; asm("tanh.approx.f32 %0, %1;" : "=f"(y) : "f"(x)); return y;
}

struct SD { u64 s0, s1, d0, d1; };          // x-smooth / x-diff, 2 pairs each
struct Fresh { u64 A0, A1, Bx0, Bx1, By0, By1; };
struct State {                              // per image, streaming partials
    u64 Am[2], Ac[2];   // A[c-1], A[c]
    u64 Ux[2], Cx[2];   // Bx[c-1]+2Bx[c],  Bx[c]
    u64 Uy[2], Cy[2];   // By[c-1]+2By[c],  By[c]
};

// x-pass for one row: s = [1,2,1]*x, d = [-1,0,1]*x, zero-padded.
__device__ __forceinline__ SD row_sd(const float* __restrict__ row, bool ok, bool xl, bool xr) {
    float4 c = make_float4(0.f, 0.f, 0.f, 0.f);
    if (ok) c = __ldg(reinterpret_cast<const float4*>(row));
    float vm = (ok && xl) ? __ldg(row - 1) : 0.f;
    float vp = (ok && xr) ? __ldg(row + 4) : 0.f;
    u64 C01 = pk(c.x, c.y), C23 = pk(c.z, c.w);
    u64 Lm  = pk(vm, c.x);          // left-shifted pair, lanes (j=0,1)
    u64 M   = pk(c.y, c.z);         // shared: right of pair0, left of pair1
    u64 R   = pk(c.w, vp);
    SD r;
    r.s0 = fma2(TWO2, C01, add2(Lm, M));
    r.s1 = fma2(TWO2, C23, add2(M, R));
    r.d0 = sub2(M, Lm);
    r.d1 = sub2(R, M);
    return r;
}

// y-pass folding rows (gy-1, gy, gy+1) of one plane.
__device__ __forceinline__ Fresh plane(const float* rm, const float* rc, const float* rp,
                                       bool zok, bool ymok, bool ypok, bool xl, bool xr) {
    SD a = row_sd(rm, zok && ymok, xl, xr);
    SD b = row_sd(rc, zok,         xl, xr);
    SD c = row_sd(rp, zok && ypok, xl, xr);
    Fresh f;
    f.A0  = fma2(TWO2, b.s0, add2(a.s0, c.s0));
    f.A1  = fma2(TWO2, b.s1, add2(a.s1, c.s1));
    f.By0 = sub2(a.s0, c.s0);
    f.By1 = sub2(a.s1, c.s1);
    f.Bx0 = fma2(TWO2, b.d0, add2(a.d0, c.d0));
    f.Bx1 = fma2(TWO2, b.d1, add2(a.d1, c.d1));
    return f;
}

__device__ __forceinline__ void state_init(State& s, const Fresh& fm1, const Fresh& f0) {
    s.Am[0] = fm1.A0;  s.Am[1] = fm1.A1;
    s.Ac[0] = f0.A0;   s.Ac[1] = f0.A1;
    s.Ux[0] = fma2(TWO2, f0.Bx0, fm1.Bx0);  s.Cx[0] = f0.Bx0;
    s.Ux[1] = fma2(TWO2, f0.Bx1, fm1.Bx1);  s.Cx[1] = f0.Bx1;
    s.Uy[0] = fma2(TWO2, f0.By0, fm1.By0);  s.Cy[0] = f0.By0;
    s.Uy[1] = fma2(TWO2, f0.By1, fm1.By1);  s.Cy[1] = f0.By1;
}

// z-combine at plane c given fresh plane c+1; updates streaming state.
__device__ __forceinline__ void step_img(State& s, const Fresh& f, u64 msq[2]) {
#pragma unroll
    for (int p = 0; p < 2; p++) {
        u64 Bx = (p == 0) ? f.Bx0 : f.Bx1;
        u64 By = (p == 0) ? f.By0 : f.By1;
        u64 A  = (p == 0) ? f.A0  : f.A1;
        u64 gx = add2(s.Ux[p], Bx);
        u64 gy = add2(s.Uy[p], By);
        u64 gz = sub2(s.Am[p], A);
        msq[p] = fma2(gx, gx, fma2(gy, gy, fma2(gz, gz, EPS2)));
        s.Ux[p] = fma2(TWO2, Bx, s.Cx[p]);  s.Cx[p] = Bx;
        s.Uy[p] = fma2(TWO2, By, s.Cy[p]);  s.Cy[p] = By;
        s.Am[p] = s.Ac[p];                  s.Ac[p] = A;
    }
}

__global__ void __launch_bounds__(THREADS, 5)
k_loss(const float* __restrict__ pred,
       const float* __restrict__ gt,
       const float* __restrict__ mask,
       float* __restrict__ out) {
    int t   = blockIdx.x * THREADS + threadIdx.x;
    int xg  = t % GX;
    int tmp = t / GX;
    int gy  = tmp % H;  tmp /= H;
    int zc  = tmp % NZ;
    int b   = tmp / NZ;
    int x0  = xg * XV;
    int z0  = zc * ZC;

    const bool ymok = (gy > 0), ypok = (gy < H - 1);
    const bool xl = (x0 > 0), xr = (x0 + XV < W);

    const size_t base = (size_t)b * D * DS + (size_t)gy * W + x0;
    // row pointers at plane z0-1 (may be out of range; loads are predicated)
    const float* rPc = pred + base + (long long)(z0 - 1) * DS;
    const float* rGc = gt   + base + (long long)(z0 - 1) * DS;
    const float* rPm = rPc - W, * rPp = rPc + W;
    const float* rGm = rGc - W, * rGp = rGc + W;
    const float* mrow = mask + base + (long long)(z0 - 1) * DS;

    // Prologue: planes z0-1 and z0
    Fresh fPm1 = plane(rPm, rPc, rPp, z0 > 0, ymok, ypok, xl, xr);
    Fresh fGm1 = plane(rGm, rGc, rGp, z0 > 0, ymok, ypok, xl, xr);
    rPm += DS; rPc += DS; rPp += DS; rGm += DS; rGc += DS; rGp += DS;
    Fresh fP0 = plane(rPm, rPc, rPp, true, ymok, ypok, xl, xr);
    Fresh fG0 = plane(rGm, rGc, rGp, true, ymok, ypok, xl, xr);

    State sP, sG;
    state_init(sP, fPm1, fP0);
    state_init(sG, fGm1, fG0);

    float acc = 0.f;
#pragma unroll 2
    for (int c = z0; c < z0 + ZC; c++) {
        rPm += DS; rPc += DS; rPp += DS; rGm += DS; rGc += DS; rGp += DS; mrow += DS;
        bool zok = (c + 1 < D);
        Fresh fP = plane(rPm, rPc, rPp, zok, ymok, ypok, xl, xr);
        Fresh fG = plane(rGm, rGc, rGp, zok, ymok, ypok, xl, xr);

        u64 msqP[2], msqG[2];
        step_img(sP, fP, msqP);
        step_img(sG, fG, msqG);

        // plane-c center values (L1-resident: loaded as row centers last iter)
        float4 pv = __ldg(reinterpret_cast<const float4*>(rPc - DS));
        float4 gv = __ldg(reinterpret_cast<const float4*>(rGc - DS));
        float4 mv = __ldg(reinterpret_cast<const float4*>(mrow));

        float mp[4], mg[4];
        { float a0,a1,a2,a3,b0,b1,b2,b3;
          upk(msqP[0], a0, a1); upk(msqP[1], a2, a3);
          upk(msqG[0], b0, b1); upk(msqG[1], b2, b3);
          mp[0]=fsqrt_a(a0); mp[1]=fsqrt_a(a1); mp[2]=fsqrt_a(a2); mp[3]=fsqrt_a(a3);
          mg[0]=fsqrt_a(b0); mg[1]=fsqrt_a(b1); mg[2]=fsqrt_a(b2); mg[3]=fsqrt_a(b3); }

        const float pvj[4] = { pv.x, pv.y, pv.z, pv.w };
        const float gvj[4] = { gv.x, gv.y, gv.z, gv.w };
        const float mvj[4] = { mv.x, mv.y, mv.z, mv.w };
#pragma unroll
        for (int j = 0; j < 4; j++) {
            float d   = pvj[j] - gvj[j];
            float mse = d * d * mvj[j];
            float dm  = mg[j] - mp[j];
            float mge = dm * dm * mvj[j];
            acc += fmaf(htanh(mge), mse, mse);
        }
    }

    // Block reduction -> one fp64 atomic; last block finalizes + re-arms
#pragma unroll
    for (int o = 16; o; o >>= 1) acc += __shfl_xor_sync(0xffffffffu, acc, o);
    __shared__ float ws[THREADS / 32];
    int lane = threadIdx.x & 31, wid = threadIdx.x >> 5;
    if (lane == 0) ws[wid] = acc;
    __syncthreads();
    if (threadIdx.x == 0) {
        float s = ws[0] + ws[1] + ws[2] + ws[3];
        atomicAdd(&g_accum, (double)s);
        __threadfence();
        unsigned tk = atomicAdd(&g_done, 1u);
        if (tk == (unsigned)gridDim.x - 1u) {
            double total = atomicAdd(&g_accum, 0.0);
            out[0] = (float)(total / (double)NVOX);
            g_accum = 0.0;
            g_done  = 0;
        }
    }
}

extern "C" void kernel_launch(void* const* d_in, const int* in_sizes, int n_in,
                              void* d_out, int out_size) {
    k_loss<<<NBLOCKS, THREADS>>>((const float*)d_in[0], (const float*)d_in[1],
                                 (const float*)d_in[2], (float*)d_out);
}

// round 4
// speedup vs baseline: 1.2070x; 1.2070x over previous
#include <cuda_runtime.h>

// Geometry fixed by the reference: (2,1,192,192,192) fp32 x3 -> scalar
constexpr int BATCH = 2, D = 192, H = 192, W = 192;
constexpr int DS = H * W;             // plane stride (elements)
constexpr int XV = 4;                 // x-values per thread (one float4)
constexpr int ZC = 16;                // z planes per thread
constexpr int GX = W / XV;            // 48
constexpr int NZ = D / ZC;            // 12
constexpr int THREADS = 128;
constexpr long long NVOX = (long long)BATCH * D * H * W;
constexpr int NBLOCKS = BATCH * H * GX * NZ / THREADS;   // 1728

__device__ double   g_accum = 0.0;
__device__ unsigned g_done  = 0;

__device__ __forceinline__ float fsqrt_a(float x) {
    float y; asm("sqrt.approx.f32 %0, %1;" : "=f"(y) : "f"(x)); return y;
}
__device__ __forceinline__ float htanh(float x) {
    float y; asm("tanh.approx.f32 %0, %1;" : "=f"(y) : "f"(x)); return y;
}

struct Fresh { float A[XV], Bx[XV], By[XV]; };

// Per-image streaming state (z-direction partial sums), 24 regs each:
//   Am/Ac = A at planes c-1 / c            (gz = Am - A[c+1])
//   Ux/Cx = Bx[c-1]+2*Bx[c] / Bx[c]        (gx = Ux + Bx[c+1])
//   Uy/Cy = By[c-1]+2*By[c] / By[c]        (gy = Uy + By[c+1])
struct State { float Am[XV], Ac[XV], Ux[XV], Cx[XV], Uy[XV], Cy[XV]; };

// x-pass for one row (addressed relative to p with immediate offsets):
// s = [1,2,1]*x  (smooth), d = x[+1]-x[-1]  (diff), zero-padded OOB.
__device__ __forceinline__ void row_sd(const float* __restrict__ p, bool ok, bool xl, bool xr,
                                       float s[XV], float d[XV]) {
    float v0 = 0.f, v1 = 0.f, v2 = 0.f, v3 = 0.f, vm = 0.f, vp = 0.f;
    if (ok) {
        float4 c = __ldg(reinterpret_cast<const float4*>(p));
        v0 = c.x; v1 = c.y; v2 = c.z; v3 = c.w;
        if (xl) vm = __ldg(p - 1);
        if (xr) vp = __ldg(p + XV);
    }
    s[0] = fmaf(2.f, v0, vm + v1);
    s[1] = fmaf(2.f, v1, v0 + v2);
    s[2] = fmaf(2.f, v2, v1 + v3);
    s[3] = fmaf(2.f, v3, v2 + vp);
    d[0] = v1 - vm;
    d[1] = v2 - v0;
    d[2] = v3 - v1;
    d[3] = vp - v2;
}

// In-plane separable pass: fold rows (gy-1, gy, gy+1) of the plane whose
// center row is at pc.  A = sy(sx), By = dy(sx), Bx = sy(dx).
__device__ __forceinline__ Fresh plane_pass(const float* __restrict__ pc, bool zok,
                                            bool ymok, bool ypok, bool xl, bool xr) {
    float sa[XV], da[XV], sb[XV], db[XV], sc[XV], dc[XV];
    row_sd(pc - W, zok && ymok, xl, xr, sa, da);
    row_sd(pc,     zok,         xl, xr, sb, db);
    row_sd(pc + W, zok && ypok, xl, xr, sc, dc);
    Fresh f;
#pragma unroll
    for (int j = 0; j < XV; j++) {
        f.A[j]  = fmaf(2.f, sb[j], sa[j] + sc[j]);
        f.By[j] = sa[j] - sc[j];
        f.Bx[j] = fmaf(2.f, db[j], da[j] + dc[j]);
    }
    return f;
}

__device__ __forceinline__ void state_init(State& s, const Fresh& fm1, const Fresh& f0) {
#pragma unroll
    for (int j = 0; j < XV; j++) {
        s.Am[j] = fm1.A[j];
        s.Ac[j] = f0.A[j];
        s.Ux[j] = fmaf(2.f, f0.Bx[j], fm1.Bx[j]);  s.Cx[j] = f0.Bx[j];
        s.Uy[j] = fmaf(2.f, f0.By[j], fm1.By[j]);  s.Cy[j] = f0.By[j];
    }
}

// z-combine at plane c given fresh plane c+1; advances streaming state.
__device__ __forceinline__ void step_img(State& s, const Fresh& f, float msq[XV]) {
#pragma unroll
    for (int j = 0; j < XV; j++) {
        float gx = s.Ux[j] + f.Bx[j];
        float gy = s.Uy[j] + f.By[j];
        float gz = s.Am[j] - f.A[j];
        msq[j] = fmaf(gx, gx, fmaf(gy, gy, fmaf(gz, gz, 1e-10f)));
        s.Ux[j] = fmaf(2.f, f.Bx[j], s.Cx[j]);  s.Cx[j] = f.Bx[j];
        s.Uy[j] = fmaf(2.f, f.By[j], s.Cy[j]);  s.Cy[j] = f.By[j];
        s.Am[j] = s.Ac[j];                      s.Ac[j] = f.A[j];
    }
}

__global__ void __launch_bounds__(THREADS, 5)
k_loss(const float* __restrict__ pred,
       const float* __restrict__ gt,
       const float* __restrict__ mask,
       float* __restrict__ out) {
    int t   = blockIdx.x * THREADS + threadIdx.x;
    int xg  = t % GX;
    int tmp = t / GX;
    int gy  = tmp % H;  tmp /= H;
    int zc  = tmp % NZ;
    int b   = tmp / NZ;
    int x0  = xg * XV;
    int z0  = zc * ZC;

    const bool ymok = (gy > 0), ypok = (gy < H - 1);
    const bool xl = (x0 > 0), xr = (x0 + XV < W);

    const size_t base = (size_t)b * D * DS + (size_t)gy * W + x0;
    // single pointer per array, positioned at plane z0-1 center row
    const float* pP = pred + base + (long long)(z0 - 1) * DS;
    const float* pG = gt   + base + (long long)(z0 - 1) * DS;
    const float* pM = mask + base + (long long)(z0 - 1) * DS;

    // Prologue: planes z0-1 and z0
    Fresh fPm1 = plane_pass(pP, z0 > 0, ymok, ypok, xl, xr);
    Fresh fGm1 = plane_pass(pG, z0 > 0, ymok, ypok, xl, xr);
    pP += DS; pG += DS;
    Fresh fP0 = plane_pass(pP, true, ymok, ypok, xl, xr);
    Fresh fG0 = plane_pass(pG, true, ymok, ypok, xl, xr);

    State sP, sG;
    state_init(sP, fPm1, fP0);
    state_init(sG, fGm1, fG0);

    float acc = 0.f;
#pragma unroll 2
    for (int c = z0; c < z0 + ZC; c++) {
        pP += DS; pG += DS; pM += DS;               // pP/pG at plane c+1, pM at plane c
        const bool zok = (c + 1 < D);
        Fresh fP = plane_pass(pP, zok, ymok, ypok, xl, xr);
        Fresh fG = plane_pass(pG, zok, ymok, ypok, xl, xr);

        float msqP[XV], msqG[XV];
        step_img(sP, fP, msqP);
        step_img(sG, fG, msqG);

        // plane-c center values (L1-resident: were loaded as row centers last iter)
        float4 pv = __ldg(reinterpret_cast<const float4*>(pP - DS));
        float4 gv = __ldg(reinterpret_cast<const float4*>(pG - DS));
        float4 mv = __ldg(reinterpret_cast<const float4*>(pM));

        const float pvj[XV] = { pv.x, pv.y, pv.z, pv.w };
        const float gvj[XV] = { gv.x, gv.y, gv.z, gv.w };
        const float mvj[XV] = { mv.x, mv.y, mv.z, mv.w };
#pragma unroll
        for (int j = 0; j < XV; j++) {
            float magp = fsqrt_a(msqP[j]);
            float magg = fsqrt_a(msqG[j]);
            float d    = pvj[j] - gvj[j];
            float mse  = d * d * mvj[j];
            float dm   = magg - magp;
            float mge  = dm * dm * mvj[j];
            acc += fmaf(htanh(mge), mse, mse);
        }
    }

    // Block reduction -> one fp64 atomic; last block finalizes + re-arms
#pragma unroll
    for (int o = 16; o; o >>= 1) acc += __shfl_xor_sync(0xffffffffu, acc, o);
    __shared__ float ws[THREADS / 32];
    int lane = threadIdx.x & 31, wid = threadIdx.x >> 5;
    if (lane == 0) ws[wid] = acc;
    __syncthreads();
    if (threadIdx.x == 0) {
        float s = ws[0] + ws[1] + ws[2] + ws[3];
        atomicAdd(&g_accum, (double)s);
        __threadfence();
        unsigned tk = atomicAdd(&g_done, 1u);
        if (tk == (unsigned)gridDim.x - 1u) {
            double total = atomicAdd(&g_accum, 0.0);
            out[0] = (float)(total / (double)NVOX);
            g_accum = 0.0;
            g_done  = 0;
        }
    }
}

extern "C" void kernel_launch(void* const* d_in, const int* in_sizes, int n_in,
                              void* d_out, int out_size) {
    k_loss<<<NBLOCKS, THREADS>>>((const float*)d_in[0], (const float*)d_in[1],
                                 (const float*)d_in[2], (float*)d_out);
}